// round 1
// baseline (speedup 1.0000x reference)
#include <cuda_runtime.h>

#define N_  4
#define C_  128
#define H_  128
#define W_  128
#define OC  8          // 2*KH*KW offset channels
#define OH  (H_*2)
#define OW  (W_*2)

// 2 MB scratch for conv offsets: [n][o][h][w], o = p*2 + d (d=0 dy, d=1 dx)
__device__ float g_off[N_*OC*H_*W_];

// ---------------------------------------------------------------------------
// Kernel 1: 3x3 SAME conv, 128 -> 8 channels, + bias.
// Block = 256 threads = 16x16 pixel tile. Weights fully resident in smem
// (broadcast LDS), x staged 8 channels at a time with halo.
// ---------------------------------------------------------------------------
#define TS 16

__global__ __launch_bounds__(256) void conv_off_kernel(
    const float* __restrict__ x,
    const float* __restrict__ wt,   // [o][c][3][3]
    const float* __restrict__ bs)   // [o]
{
    __shared__ float ws[C_*9*OC];   // [(c*9+tap)*8 + o]
    __shared__ float xs[8][18*18];  // 8 channels, 18x18 halo tile

    const int n  = blockIdx.z;
    const int h0 = blockIdx.y * TS;
    const int w0 = blockIdx.x * TS;
    const int tid = threadIdx.x;
    const int tx = tid & 15;
    const int ty = tid >> 4;

    // Load + transpose weights into smem: dst[(c*9+tap)*8+o] = wt[(o*C+c)*9+tap]
    for (int i = tid; i < C_*9*OC; i += 256) {
        int o  = i & 7;
        int ct = i >> 3;           // c*9 + tap
        int c  = ct / 9;
        int tap = ct - c*9;
        ws[i] = wt[(o*C_ + c)*9 + tap];
    }

    float acc[OC];
#pragma unroll
    for (int o = 0; o < OC; o++) acc[o] = __ldg(&bs[o]);

    const float* xn = x + (size_t)n * C_*H_*W_;

    for (int c0 = 0; c0 < C_; c0 += 8) {
        __syncthreads();   // covers weight load (c0==0) and prev-chunk compute
        // Stage 8 channels of the 18x18 halo tile (zero-padded)
        for (int i = tid; i < 8*18*18; i += 256) {
            int cc = i / (18*18);
            int r  = i - cc*(18*18);
            int ly = r / 18;
            int lx = r - ly*18;
            int gy = h0 - 1 + ly;
            int gx = w0 - 1 + lx;
            float v = 0.f;
            if ((unsigned)gy < H_ && (unsigned)gx < W_)
                v = xn[(c0+cc)*H_*W_ + gy*W_ + gx];
            xs[cc][r] = v;
        }
        __syncthreads();

#pragma unroll
        for (int cc = 0; cc < 8; cc++) {
            float xv[9];
#pragma unroll
            for (int ky = 0; ky < 3; ky++)
#pragma unroll
                for (int kx = 0; kx < 3; kx++)
                    xv[ky*3+kx] = xs[cc][(ty+ky)*18 + (tx+kx)];

            const float* wp = &ws[(c0+cc)*9*OC];
#pragma unroll
            for (int tap = 0; tap < 9; tap++) {
#pragma unroll
                for (int o = 0; o < OC; o++)
                    acc[o] += xv[tap] * wp[tap*OC + o];
            }
        }
    }

    const int h = h0 + ty;
    const int w = w0 + tx;
#pragma unroll
    for (int o = 0; o < OC; o++)
        g_off[((n*OC + o)*H_ + h)*W_ + w] = acc[o];
}

// ---------------------------------------------------------------------------
// Kernel 2: bilinear sampling + pixel shuffle.
// One block per (n, h, kh) output row-pair; offsets for the row staged once
// in smem and reused for all 128 channels. Each thread writes a float2
// (kw=0,1) per channel iteration.
// ---------------------------------------------------------------------------
__device__ __forceinline__ float fetch0(const float* __restrict__ xp, int y, int xx) {
    if ((unsigned)y < H_ && (unsigned)xx < W_)
        return __ldg(xp + y*W_ + xx);
    return 0.f;
}

__global__ __launch_bounds__(256) void sample_kernel(
    const float* __restrict__ x,
    float* __restrict__ out)
{
    // blockIdx.x in [0, 1024): bit0 = kh, bits1..7 = h, bits8.. = n
    const int b  = blockIdx.x;
    const int kh = b & 1;
    const int h  = (b >> 1) & (H_-1);
    const int n  = b >> 8;

    const int tid = threadIdx.x;
    const int w   = tid & (W_-1);   // 0..127
    const int ci  = tid >> 7;       // 0..1

    // soff[j][w]: j=0 dy(kw=0), 1 dx(kw=0), 2 dy(kw=1), 3 dx(kw=1)
    __shared__ float soff[4][W_];
    for (int i = tid; i < 4*W_; i += 256) {
        int j  = i >> 7;           // 0..3
        int ww = i & (W_-1);
        int p  = kh*2 + (j >> 1);  // kernel position
        int o  = p*2 + (j & 1);    // offset channel
        soff[j][ww] = g_off[((n*OC + o)*H_ + h)*W_ + ww];
    }
    __syncthreads();

    // Precompute per-thread sample geometry (same for all channels)
    float syA = (float)h + soff[0][w];
    float sxA = (float)w + soff[1][w];
    float syB = (float)h + soff[2][w];
    float sxB = (float)w + soff[3][w];

    float y0Af = floorf(syA), x0Af = floorf(sxA);
    float y0Bf = floorf(syB), x0Bf = floorf(sxB);
    int y0A = (int)y0Af, x0A = (int)x0Af;
    int y0B = (int)y0Bf, x0B = (int)x0Bf;
    float wyA = syA - y0Af, wxA = sxA - x0Af;
    float wyB = syB - y0Bf, wxB = sxB - x0Bf;

    // bilinear corner weights
    float cA00 = (1.f - wyA) * (1.f - wxA);
    float cA01 = (1.f - wyA) * wxA;
    float cA10 = wyA * (1.f - wxA);
    float cA11 = wyA * wxA;
    float cB00 = (1.f - wyB) * (1.f - wxB);
    float cB01 = (1.f - wyB) * wxB;
    float cB10 = wyB * (1.f - wxB);
    float cB11 = wyB * wxB;

    const int oh = 2*h + kh;
    const size_t out_row_base = ((size_t)n*C_)*OH*OW + (size_t)oh*OW + 2*w;

    for (int c0 = 0; c0 < C_; c0 += 2) {
        const int c = c0 + ci;
        const float* xp = x + ((size_t)n*C_ + c)*H_*W_;

        float rA = fetch0(xp, y0A,   x0A  ) * cA00
                 + fetch0(xp, y0A,   x0A+1) * cA01
                 + fetch0(xp, y0A+1, x0A  ) * cA10
                 + fetch0(xp, y0A+1, x0A+1) * cA11;
        float rB = fetch0(xp, y0B,   x0B  ) * cB00
                 + fetch0(xp, y0B,   x0B+1) * cB01
                 + fetch0(xp, y0B+1, x0B  ) * cB10
                 + fetch0(xp, y0B+1, x0B+1) * cB11;

        float2 v = make_float2(rA, rB);
        *reinterpret_cast<float2*>(out + out_row_base + (size_t)c*OH*OW) = v;
    }
}

// ---------------------------------------------------------------------------
extern "C" void kernel_launch(void* const* d_in, const int* in_sizes, int n_in,
                              void* d_out, int out_size)
{
    const float* x  = (const float*)d_in[0];
    const float* wt = (const float*)d_in[1];
    const float* bs = (const float*)d_in[2];
    float* out = (float*)d_out;

    conv_off_kernel<<<dim3(W_/TS, H_/TS, N_), 256>>>(x, wt, bs);
    sample_kernel<<<N_*H_*2, 256>>>(x, out);
}